// round 7
// baseline (speedup 1.0000x reference)
#include <cuda_runtime.h>
#include <cuda_fp16.h>
#include <cstdint>
#include <cstddef>

// ---------------------------------------------------------------------------
// Problem constants (fixed shapes)
// ---------------------------------------------------------------------------
static constexpr int MDIM = 8192;   // B*S
static constexpr int NDIM = 4096;   // D_OUT
static constexpr int KDIM = 4096;   // D_IN

static constexpr int MT = 128;      // M tile per CTA
static constexpr int NT = 256;      // N tile per CTA
static constexpr int KTB = 64;      // K per tile block (storage granularity)
static constexpr int KB  = KDIM / KTB;        // 64 blocks
static constexpr int KT  = 128;     // K per pipeline stage (2 blocks)
static constexpr int KS  = KDIM / KT;         // 32 stages of work
static constexpr int NSTAGE = 2;

static constexpr int A_BLK_BYTES = MT * KTB * 2;          // 16384
static constexpr int W_BLK_BYTES = NT * KTB * 2;          // 32768
static constexpr int A_STAGE_BYTES = 2 * A_BLK_BYTES;     // 32768
static constexpr int W_STAGE_BYTES = 2 * W_BLK_BYTES;     // 65536
static constexpr int STAGE_BYTES = A_STAGE_BYTES + W_STAGE_BYTES; // 98304

static constexpr int SMEM_TOTAL = 1024 + NSTAGE * STAGE_BYTES;    // 197632

// Weight-conversion grid: 8 elements per thread, 256 threads per block.
static constexpr int WCONV_BLOCKS = NDIM * KDIM / 8 / 256;        // 8192

// ---------------------------------------------------------------------------
// Scratch (device globals). Pre-swizzled (SW128) SMEM-ready tile blocks:
//   A (x in fp16):   [mb(64)][kb(64)] blocks of 128 rows x 128B, 16KB each
//   W (q-8 in fp16): [nbp(16)][kb(64)] blocks of 256 rows x 128B, 32KB each
// ---------------------------------------------------------------------------
__device__ __align__(1024) unsigned char g_Ah[(size_t)MDIM * KDIM * 2];
__device__ __align__(1024) unsigned char g_Wb[(size_t)NDIM * KDIM * 2];
__device__ float g_rowsum[MDIM];

// ---------------------------------------------------------------------------
// PTX helpers (base PTX only — nothing 'a'-gated)
// ---------------------------------------------------------------------------
__device__ __forceinline__ uint32_t smem_u32(const void* p) {
    uint32_t a;
    asm("{ .reg .u64 t; cvta.to.shared.u64 t, %1; cvt.u32.u64 %0, t; }"
        : "=r"(a) : "l"(p));
    return a;
}

__device__ __forceinline__ uint32_t swz(uint32_t b) {
    return b ^ ((b >> 3) & 0x70);
}

__device__ __forceinline__ void mbar_init(uint32_t mbar, uint32_t cnt) {
    asm volatile("mbarrier.init.shared.b64 [%0], %1;" :: "r"(mbar), "r"(cnt) : "memory");
}

__device__ __forceinline__ void mbar_arrive(uint32_t mbar) {
    asm volatile("mbarrier.arrive.shared.b64 _, [%0];" :: "r"(mbar) : "memory");
}

__device__ __forceinline__ void mbar_expect_tx(uint32_t mbar, uint32_t bytes) {
    asm volatile("mbarrier.arrive.expect_tx.shared.b64 _, [%0], %1;"
                 :: "r"(mbar), "r"(bytes) : "memory");
}

__device__ __forceinline__ void bar_wait(uint32_t mbar, uint32_t parity) {
    uint32_t done;
    asm volatile("{\n .reg .pred p;\n"
                 " mbarrier.try_wait.parity.acquire.cta.shared::cta.b64 p, [%1], %2;\n"
                 " selp.b32 %0, 1, 0, p;\n}"
                 : "=r"(done) : "r"(mbar), "r"(parity) : "memory");
    while (!done) {
        asm volatile("{\n .reg .pred p;\n"
                     " mbarrier.try_wait.parity.acquire.cta.shared::cta.b64 p, [%1], %2, 0x989680;\n"
                     " selp.b32 %0, 1, 0, p;\n}"
                     : "=r"(done) : "r"(mbar), "r"(parity) : "memory");
    }
}

__device__ __forceinline__ void bulk_g2s(uint32_t dst_smem, const void* src,
                                         uint32_t bytes, uint32_t mbar) {
    asm volatile(
        "cp.async.bulk.shared::cluster.global.mbarrier::complete_tx::bytes "
        "[%0], [%1], %2, [%3];"
        :: "r"(dst_smem), "l"(src), "r"(bytes), "r"(mbar) : "memory");
}

__device__ __forceinline__ void ldsm_x4(uint32_t& r0, uint32_t& r1,
                                        uint32_t& r2, uint32_t& r3, uint32_t addr) {
    asm volatile("ldmatrix.sync.aligned.m8n8.x4.shared.b16 {%0,%1,%2,%3}, [%4];"
                 : "=r"(r0), "=r"(r1), "=r"(r2), "=r"(r3) : "r"(addr));
}

__device__ __forceinline__ void mma_f16(float* c, uint32_t a0, uint32_t a1,
                                        uint32_t a2, uint32_t a3,
                                        uint32_t b0, uint32_t b1) {
    asm volatile("mma.sync.aligned.m16n8k16.row.col.f32.f16.f16.f32 "
                 "{%0,%1,%2,%3}, {%4,%5,%6,%7}, {%8,%9}, {%0,%1,%2,%3};"
                 : "+f"(c[0]), "+f"(c[1]), "+f"(c[2]), "+f"(c[3])
                 : "r"(a0), "r"(a1), "r"(a2), "r"(a3), "r"(b0), "r"(b1));
}

__device__ __forceinline__ uint32_t pack_h2f(float lo, float hi) {
    __half2 t = __floats2half2_rn(lo, hi);
    return *reinterpret_cast<uint32_t*>(&t);
}

// ---------------------------------------------------------------------------
// Fused prep: blocks [0, MDIM) convert x rows; blocks [MDIM, MDIM+WCONV_BLOCKS)
// convert weights (8 elems/thread).
// ---------------------------------------------------------------------------
__global__ void prep_kernel(const float* __restrict__ x, const int* __restrict__ q) {
    if (blockIdx.x < MDIM) {
        // ---- x fp32 -> fp16 plane (swizzled) + exact fp32 row sum ----
        const int m = blockIdx.x;
        const int t = threadIdx.x;    // 256 threads
        const float4* row = reinterpret_cast<const float4*>(x + (size_t)m * KDIM);
        const int mbb = m >> 7;
        const int r   = m & 127;
        const size_t abase = (size_t)mbb * ((size_t)KB * A_BLK_BYTES);

        float sum = 0.f;
        #pragma unroll
        for (int i = 0; i < 4; i++) {
            int g = t + i * 256;
            float4 v = row[g];
            sum += (v.x + v.y) + (v.z + v.w);

            int k0 = g << 2;
            int kb = k0 >> 6;
            int c0 = k0 & 63;
            size_t off = abase + (size_t)kb * A_BLK_BYTES
                       + swz((uint32_t)(r * 128 + c0 * 2));
            *reinterpret_cast<uint2*>(g_Ah + off) =
                make_uint2(pack_h2f(v.x, v.y), pack_h2f(v.z, v.w));
        }

        #pragma unroll
        for (int o = 16; o; o >>= 1) sum += __shfl_xor_sync(0xFFFFFFFFu, sum, o);
        __shared__ float ws[8];
        if ((t & 31) == 0) ws[t >> 5] = sum;
        __syncthreads();
        if (t == 0) {
            float s = 0.f;
            #pragma unroll
            for (int i = 0; i < 8; i++) s += ws[i];
            g_rowsum[m] = s;
        }
    } else {
        // ---- weight int32 (0..15) -> fp16 (q-8, exact), SW128 blocks ----
        int idx = (blockIdx.x - MDIM) * blockDim.x + threadIdx.x; // 8 elems/thr
        int n  = idx >> 9;            // 512 groups of 8 per row
        int k0 = (idx & 511) << 3;

        const int4* p = reinterpret_cast<const int4*>(q + (size_t)n * KDIM + k0);
        int4 a = p[0], b = p[1];
        uint32_t w0 = pack_h2f((float)(a.x - 8), (float)(a.y - 8));
        uint32_t w1 = pack_h2f((float)(a.z - 8), (float)(a.w - 8));
        uint32_t w2 = pack_h2f((float)(b.x - 8), (float)(b.y - 8));
        uint32_t w3 = pack_h2f((float)(b.z - 8), (float)(b.w - 8));

        int nbp = n >> 8;
        int r   = n & 255;
        int kb  = k0 >> 6;
        int c0  = k0 & 63;
        size_t off = ((size_t)(nbp * KB + kb)) * W_BLK_BYTES
                   + swz((uint32_t)(r * 128 + c0 * 2));
        *reinterpret_cast<uint4*>(g_Wb + off) = make_uint4(w0, w1, w2, w3);
    }
}

// ---------------------------------------------------------------------------
// GEMM: 128x256 CTA tile. 8 compute warps (each 32x128) + 1 producer warp.
// KT=128 stages (2 SW128 blocks per stage), NSTAGE=2. Single fp16 plane;
// y = scl*G + scl*(8-zp)*rowsum + bias.
// ---------------------------------------------------------------------------
__global__ void __launch_bounds__(288, 1)
qgemm_kernel(const float* __restrict__ scale_p,
             const float* __restrict__ zp_p,
             const float* __restrict__ bias,
             float* __restrict__ out)
{
    extern __shared__ __align__(1024) unsigned char smem[];
    const uint32_t sb = smem_u32(smem);
    const int tid = threadIdx.x;
    const int wid = tid >> 5;            // 0..8
    const int lid = tid & 31;
    const int mb  = blockIdx.y;          // 0..63
    const int nbp = blockIdx.x;          // 0..15

    const uint32_t FULLB  = sb;          // 2 x 8B
    const uint32_t EMPTYB = sb + 32;     // 2 x 8B
    const uint32_t TILE0  = sb + 1024;

    if (tid == 0) {
        #pragma unroll
        for (int s = 0; s < NSTAGE; s++) {
            mbar_init(FULLB  + 8 * s, 1);
            mbar_init(EMPTYB + 8 * s, 8);
        }
        asm volatile("fence.proxy.async.shared::cta;" ::: "memory");
    }
    __syncthreads();

    if (wid < 8 && lid == 0) {
        #pragma unroll
        for (int s = 0; s < NSTAGE; s++) mbar_arrive(EMPTYB + 8 * s);
    }

    if (wid == 8) {
        // ------------------------- producer -------------------------
        if (lid == 0) {
            const unsigned char* aB = g_Ah + (size_t)mb  * ((size_t)KB * A_BLK_BYTES);
            const unsigned char* wB = g_Wb + (size_t)nbp * ((size_t)KB * W_BLK_BYTES);
            int s = 0, ph = 0;
            for (int it = 0; it < KS; it++) {
                bar_wait(EMPTYB + 8 * s, ph);
                mbar_expect_tx(FULLB + 8 * s, STAGE_BYTES);
                uint32_t d = TILE0 + s * STAGE_BYTES;
                // 2 adjacent kb blocks are contiguous in the global layout.
                bulk_g2s(d,                 aB + (size_t)it * A_STAGE_BYTES,
                         A_STAGE_BYTES, FULLB + 8 * s);
                bulk_g2s(d + A_STAGE_BYTES, wB + (size_t)it * W_STAGE_BYTES,
                         W_STAGE_BYTES, FULLB + 8 * s);
                if (++s == NSTAGE) { s = 0; ph ^= 1; }
            }
        }
        return;
    }

    // ------------------------- compute warps -------------------------
    const int wm = wid & 3;          // M sub-tile (32 rows)
    const int wn = wid >> 2;         // N sub-tile (128 cols)
    const int g  = lid >> 3;         // ldmatrix lane group 0..3
    const int lr = lid & 7;

    uint32_t aRow[2], aXor[2];
    #pragma unroll
    for (int mt = 0; mt < 2; mt++) {
        int r = wm * 32 + mt * 16 + (g & 1) * 8 + lr;
        aRow[mt] = (uint32_t)(r * 128);
        aXor[mt] = (uint32_t)((r & 7) << 4);
    }
    uint32_t bRow[8], bXor[8];
    #pragma unroll
    for (int bt = 0; bt < 8; bt++) {
        int r = wn * 128 + bt * 16 + (g >> 1) * 8 + lr;
        bRow[bt] = (uint32_t)(r * 128);
        bXor[bt] = (uint32_t)((r & 7) << 4);
    }
    const uint32_t aCol = (uint32_t)((g >> 1) * 16);
    const uint32_t bCol = (uint32_t)((g & 1) * 16);

    float acc[2][16][4];
    #pragma unroll
    for (int mt = 0; mt < 2; mt++)
        #pragma unroll
        for (int nt = 0; nt < 16; nt++)
            #pragma unroll
            for (int j = 0; j < 4; j++) acc[mt][nt][j] = 0.f;

    int s = 0, ph = 0;
    for (int it = 0; it < KS; it++) {
        bar_wait(FULLB + 8 * s, ph);
        const uint32_t dStage = TILE0 + s * STAGE_BYTES;

        #pragma unroll
        for (int blk = 0; blk < 2; blk++) {
            const uint32_t dA = dStage + blk * A_BLK_BYTES;
            const uint32_t dW = dStage + A_STAGE_BYTES + blk * W_BLK_BYTES;

            #pragma unroll
            for (int ks = 0; ks < 4; ks++) {
                const uint32_t kOff = (uint32_t)(ks * 32);

                uint32_t bf[8][4];
                #pragma unroll
                for (int bt = 0; bt < 8; bt++) {
                    uint32_t off = bRow[bt] + ((kOff + bCol) ^ bXor[bt]);
                    ldsm_x4(bf[bt][0], bf[bt][1], bf[bt][2], bf[bt][3], dW + off);
                }
                uint32_t ah[2][4];
                #pragma unroll
                for (int mt = 0; mt < 2; mt++) {
                    uint32_t off = aRow[mt] + ((kOff + aCol) ^ aXor[mt]);
                    ldsm_x4(ah[mt][0], ah[mt][1], ah[mt][2], ah[mt][3], dA + off);
                }
                #pragma unroll
                for (int bt = 0; bt < 8; bt++) {
                    #pragma unroll
                    for (int mt = 0; mt < 2; mt++) {
                        mma_f16(acc[mt][2 * bt + 0], ah[mt][0], ah[mt][1], ah[mt][2], ah[mt][3],
                                bf[bt][0], bf[bt][1]);
                        mma_f16(acc[mt][2 * bt + 1], ah[mt][0], ah[mt][1], ah[mt][2], ah[mt][3],
                                bf[bt][2], bf[bt][3]);
                    }
                }
            }
        }
        if (lid == 0) mbar_arrive(EMPTYB + 8 * s);
        if (++s == NSTAGE) { s = 0; ph ^= 1; }
    }

    // ------------------------- epilogue -------------------------
    const float scl = *scale_p;
    const float zp  = *zp_p;
    const int mRow0 = mb * MT + wm * 32;
    const int nCol0 = nbp * NT + wn * 128;

    #pragma unroll
    for (int mt = 0; mt < 2; mt++) {
        const int r0 = mRow0 + mt * 16 + (lid >> 2);
        const int r1 = r0 + 8;
        const float base0 = scl * (8.0f - zp) * g_rowsum[r0];
        const float base1 = scl * (8.0f - zp) * g_rowsum[r1];
        float* o0 = out + (size_t)r0 * NDIM;
        float* o1 = out + (size_t)r1 * NDIM;
        #pragma unroll
        for (int nt = 0; nt < 16; nt++) {
            const int c = nCol0 + nt * 8 + 2 * (lid & 3);
            const float2 bv = *reinterpret_cast<const float2*>(bias + c);
            float2 v0, v1;
            v0.x = fmaf(scl, acc[mt][nt][0], base0 + bv.x);
            v0.y = fmaf(scl, acc[mt][nt][1], base0 + bv.y);
            v1.x = fmaf(scl, acc[mt][nt][2], base1 + bv.x);
            v1.y = fmaf(scl, acc[mt][nt][3], base1 + bv.y);
            *reinterpret_cast<float2*>(o0 + c) = v0;
            *reinterpret_cast<float2*>(o1 + c) = v1;
        }
    }
}

// ---------------------------------------------------------------------------
// kernel_launch
// ---------------------------------------------------------------------------
extern "C" void kernel_launch(void* const* d_in, const int* in_sizes, int n_in,
                              void* d_out, int out_size)
{
    (void)in_sizes; (void)n_in; (void)out_size;
    const float* x     = (const float*)d_in[0];
    const int*   wq    = (const int*)  d_in[1];
    const float* scale = (const float*)d_in[2];
    const float* zp    = (const float*)d_in[3];
    const float* bias  = (const float*)d_in[4];
    float* out = (float*)d_out;

    // Fused prep: 8192 x-row blocks + 8192 weight blocks (8 elems/thread)
    prep_kernel<<<MDIM + WCONV_BLOCKS, 256>>>(x, wq);

    cudaFuncSetAttribute(qgemm_kernel,
                         cudaFuncAttributeMaxDynamicSharedMemorySize, SMEM_TOTAL);
    dim3 grid(NDIM / NT, MDIM / MT);   // (16, 64)
    qgemm_kernel<<<grid, 288, SMEM_TOTAL>>>(scale, zp, bias, out);
}

// round 8
// speedup vs baseline: 1.0569x; 1.0569x over previous
#include <cuda_runtime.h>
#include <cuda_fp16.h>
#include <cstdint>
#include <cstddef>

// ---------------------------------------------------------------------------
// Problem constants (fixed shapes)
// ---------------------------------------------------------------------------
static constexpr int MDIM = 8192;   // B*S
static constexpr int NDIM = 4096;   // D_OUT
static constexpr int KDIM = 4096;   // D_IN

static constexpr int MT = 128;      // M tile per CTA
static constexpr int NT = 256;      // N tile per CTA
static constexpr int KT = 64;       // K per pipeline stage
static constexpr int KB = KDIM / KT;          // 64 K-iterations
static constexpr int NSTAGE = 4;

static constexpr int A_TILE_BYTES = MT * KT * 2;          // 16384
static constexpr int W_TILE_BYTES = NT * KT * 2;          // 32768
static constexpr int STAGE_BYTES  = A_TILE_BYTES + W_TILE_BYTES;  // 49152

static constexpr int SMEM_TOTAL = 1024 + NSTAGE * STAGE_BYTES;    // 197632

// Weight-conversion grid: 8 elements per thread, 256 threads per block.
static constexpr int WCONV_BLOCKS = NDIM * KDIM / 8 / 256;        // 8192

// ---------------------------------------------------------------------------
// Scratch (device globals). Pre-swizzled (SW128) SMEM-ready tile blocks:
//   A (x in fp16):   [mb(64)][kb(64)] blocks of 128 rows x 128B, 16KB each
//   W (q-8 in fp16): [nbp(16)][kb(64)] blocks of 256 rows x 128B, 32KB each
// ---------------------------------------------------------------------------
__device__ __align__(1024) unsigned char g_Ah[(size_t)MDIM * KDIM * 2];
__device__ __align__(1024) unsigned char g_Wb[(size_t)NDIM * KDIM * 2];
__device__ float g_rowsum[MDIM];

// ---------------------------------------------------------------------------
// PTX helpers (base PTX only — nothing 'a'-gated)
// ---------------------------------------------------------------------------
__device__ __forceinline__ uint32_t smem_u32(const void* p) {
    uint32_t a;
    asm("{ .reg .u64 t; cvta.to.shared.u64 t, %1; cvt.u32.u64 %0, t; }"
        : "=r"(a) : "l"(p));
    return a;
}

__device__ __forceinline__ uint32_t swz(uint32_t b) {
    return b ^ ((b >> 3) & 0x70);
}

__device__ __forceinline__ void mbar_init(uint32_t mbar, uint32_t cnt) {
    asm volatile("mbarrier.init.shared.b64 [%0], %1;" :: "r"(mbar), "r"(cnt) : "memory");
}

__device__ __forceinline__ void mbar_arrive(uint32_t mbar) {
    asm volatile("mbarrier.arrive.shared.b64 _, [%0];" :: "r"(mbar) : "memory");
}

__device__ __forceinline__ void mbar_expect_tx(uint32_t mbar, uint32_t bytes) {
    asm volatile("mbarrier.arrive.expect_tx.shared.b64 _, [%0], %1;"
                 :: "r"(mbar), "r"(bytes) : "memory");
}

__device__ __forceinline__ void bar_wait(uint32_t mbar, uint32_t parity) {
    uint32_t done;
    asm volatile("{\n .reg .pred p;\n"
                 " mbarrier.try_wait.parity.acquire.cta.shared::cta.b64 p, [%1], %2;\n"
                 " selp.b32 %0, 1, 0, p;\n}"
                 : "=r"(done) : "r"(mbar), "r"(parity) : "memory");
    while (!done) {
        asm volatile("{\n .reg .pred p;\n"
                     " mbarrier.try_wait.parity.acquire.cta.shared::cta.b64 p, [%1], %2, 0x989680;\n"
                     " selp.b32 %0, 1, 0, p;\n}"
                     : "=r"(done) : "r"(mbar), "r"(parity) : "memory");
    }
}

__device__ __forceinline__ void bulk_g2s(uint32_t dst_smem, const void* src,
                                         uint32_t bytes, uint32_t mbar) {
    asm volatile(
        "cp.async.bulk.shared::cluster.global.mbarrier::complete_tx::bytes "
        "[%0], [%1], %2, [%3];"
        :: "r"(dst_smem), "l"(src), "r"(bytes), "r"(mbar) : "memory");
}

__device__ __forceinline__ void ldsm_x4(uint32_t& r0, uint32_t& r1,
                                        uint32_t& r2, uint32_t& r3, uint32_t addr) {
    asm volatile("ldmatrix.sync.aligned.m8n8.x4.shared.b16 {%0,%1,%2,%3}, [%4];"
                 : "=r"(r0), "=r"(r1), "=r"(r2), "=r"(r3) : "r"(addr));
}

__device__ __forceinline__ void mma_f16(float* c, uint32_t a0, uint32_t a1,
                                        uint32_t a2, uint32_t a3,
                                        uint32_t b0, uint32_t b1) {
    asm volatile("mma.sync.aligned.m16n8k16.row.col.f32.f16.f16.f32 "
                 "{%0,%1,%2,%3}, {%4,%5,%6,%7}, {%8,%9}, {%0,%1,%2,%3};"
                 : "+f"(c[0]), "+f"(c[1]), "+f"(c[2]), "+f"(c[3])
                 : "r"(a0), "r"(a1), "r"(a2), "r"(a3), "r"(b0), "r"(b1));
}

__device__ __forceinline__ uint32_t pack_h2f(float lo, float hi) {
    __half2 t = __floats2half2_rn(lo, hi);
    return *reinterpret_cast<uint32_t*>(&t);
}

// ---------------------------------------------------------------------------
// Fused prep: blocks [0, MDIM) convert x rows; blocks [MDIM, MDIM+WCONV_BLOCKS)
// convert weights (8 elems/thread).
// ---------------------------------------------------------------------------
__global__ void prep_kernel(const float* __restrict__ x, const int* __restrict__ q) {
    if (blockIdx.x < MDIM) {
        // ---- x fp32 -> fp16 plane (swizzled) + exact fp32 row sum ----
        const int m = blockIdx.x;
        const int t = threadIdx.x;    // 256 threads
        const float4* row = reinterpret_cast<const float4*>(x + (size_t)m * KDIM);
        const int mbb = m >> 7;
        const int r   = m & 127;
        const size_t abase = (size_t)mbb * ((size_t)KB * A_TILE_BYTES);

        float sum = 0.f;
        #pragma unroll
        for (int i = 0; i < 4; i++) {
            int g = t + i * 256;
            float4 v = row[g];
            sum += (v.x + v.y) + (v.z + v.w);

            int k0 = g << 2;
            int kb = k0 >> 6;
            int c0 = k0 & 63;
            size_t off = abase + (size_t)kb * A_TILE_BYTES
                       + swz((uint32_t)(r * 128 + c0 * 2));
            *reinterpret_cast<uint2*>(g_Ah + off) =
                make_uint2(pack_h2f(v.x, v.y), pack_h2f(v.z, v.w));
        }

        #pragma unroll
        for (int o = 16; o; o >>= 1) sum += __shfl_xor_sync(0xFFFFFFFFu, sum, o);
        __shared__ float ws[8];
        if ((t & 31) == 0) ws[t >> 5] = sum;
        __syncthreads();
        if (t == 0) {
            float s = 0.f;
            #pragma unroll
            for (int i = 0; i < 8; i++) s += ws[i];
            g_rowsum[m] = s;
        }
    } else {
        // ---- weight int32 (0..15) -> fp16 (q-8, exact), SW128 blocks ----
        int idx = (blockIdx.x - MDIM) * blockDim.x + threadIdx.x; // 8 elems/thr
        int n  = idx >> 9;            // 512 groups of 8 per row
        int k0 = (idx & 511) << 3;

        const int4* p = reinterpret_cast<const int4*>(q + (size_t)n * KDIM + k0);
        int4 a = p[0], b = p[1];
        uint32_t w0 = pack_h2f((float)(a.x - 8), (float)(a.y - 8));
        uint32_t w1 = pack_h2f((float)(a.z - 8), (float)(a.w - 8));
        uint32_t w2 = pack_h2f((float)(b.x - 8), (float)(b.y - 8));
        uint32_t w3 = pack_h2f((float)(b.z - 8), (float)(b.w - 8));

        int nbp = n >> 8;
        int r   = n & 255;
        int kb  = k0 >> 6;
        int c0  = k0 & 63;
        size_t off = ((size_t)(nbp * KB + kb)) * W_TILE_BYTES
                   + swz((uint32_t)(r * 128 + c0 * 2));
        *reinterpret_cast<uint4*>(g_Wb + off) = make_uint4(w0, w1, w2, w3);
    }
}

// ---------------------------------------------------------------------------
// GEMM: 128x256 CTA tile. 8 compute warps (each 32x128) + 1 producer warp.
// KT=64 / NSTAGE=4 (proven 93%-of-pipe config). Single fp16 plane;
// y = scl*G + scl*(8-zp)*rowsum + bias.
// ---------------------------------------------------------------------------
__global__ void __launch_bounds__(288, 1)
qgemm_kernel(const float* __restrict__ scale_p,
             const float* __restrict__ zp_p,
             const float* __restrict__ bias,
             float* __restrict__ out)
{
    extern __shared__ __align__(1024) unsigned char smem[];
    const uint32_t sb = smem_u32(smem);
    const int tid = threadIdx.x;
    const int wid = tid >> 5;            // 0..8
    const int lid = tid & 31;
    const int mb  = blockIdx.y;          // 0..63
    const int nbp = blockIdx.x;          // 0..15

    const uint32_t FULLB  = sb;          // 4 x 8B
    const uint32_t EMPTYB = sb + 64;     // 4 x 8B
    const uint32_t TILE0  = sb + 1024;

    if (tid == 0) {
        #pragma unroll
        for (int s = 0; s < NSTAGE; s++) {
            mbar_init(FULLB  + 8 * s, 1);
            mbar_init(EMPTYB + 8 * s, 8);
        }
        asm volatile("fence.proxy.async.shared::cta;" ::: "memory");
    }
    __syncthreads();

    if (wid < 8 && lid == 0) {
        #pragma unroll
        for (int s = 0; s < NSTAGE; s++) mbar_arrive(EMPTYB + 8 * s);
    }

    if (wid == 8) {
        // ------------------------- producer -------------------------
        if (lid == 0) {
            const unsigned char* aB = g_Ah + (size_t)mb  * ((size_t)KB * A_TILE_BYTES);
            const unsigned char* wB = g_Wb + (size_t)nbp * ((size_t)KB * W_TILE_BYTES);
            int s = 0, ph = 0;
            for (int kb = 0; kb < KB; kb++) {
                bar_wait(EMPTYB + 8 * s, ph);
                mbar_expect_tx(FULLB + 8 * s, STAGE_BYTES);
                uint32_t d = TILE0 + s * STAGE_BYTES;
                bulk_g2s(d,                aB + (size_t)kb * A_TILE_BYTES,
                         A_TILE_BYTES, FULLB + 8 * s);
                bulk_g2s(d + A_TILE_BYTES, wB + (size_t)kb * W_TILE_BYTES,
                         W_TILE_BYTES, FULLB + 8 * s);
                if (++s == NSTAGE) { s = 0; ph ^= 1; }
            }
        }
        return;
    }

    // ------------------------- compute warps -------------------------
    const int wm = wid & 3;          // M sub-tile (32 rows)
    const int wn = wid >> 2;         // N sub-tile (128 cols)
    const int g  = lid >> 3;         // ldmatrix lane group 0..3
    const int lr = lid & 7;

    uint32_t aRow[2], aXor[2];
    #pragma unroll
    for (int mt = 0; mt < 2; mt++) {
        int r = wm * 32 + mt * 16 + (g & 1) * 8 + lr;
        aRow[mt] = (uint32_t)(r * 128);
        aXor[mt] = (uint32_t)((r & 7) << 4);
    }
    uint32_t bRow[8], bXor[8];
    #pragma unroll
    for (int bt = 0; bt < 8; bt++) {
        int r = wn * 128 + bt * 16 + (g >> 1) * 8 + lr;
        bRow[bt] = (uint32_t)(r * 128);
        bXor[bt] = (uint32_t)((r & 7) << 4);
    }
    const uint32_t aCol = (uint32_t)((g >> 1) * 16);
    const uint32_t bCol = (uint32_t)((g & 1) * 16);

    float acc[2][16][4];
    #pragma unroll
    for (int mt = 0; mt < 2; mt++)
        #pragma unroll
        for (int nt = 0; nt < 16; nt++)
            #pragma unroll
            for (int j = 0; j < 4; j++) acc[mt][nt][j] = 0.f;

    int s = 0, ph = 0;
    for (int kb = 0; kb < KB; kb++) {
        bar_wait(FULLB + 8 * s, ph);
        const uint32_t dA = TILE0 + s * STAGE_BYTES;
        const uint32_t dW = dA + A_TILE_BYTES;

        #pragma unroll
        for (int ks = 0; ks < 4; ks++) {
            const uint32_t kOff = (uint32_t)(ks * 32);

            uint32_t bf[8][4];
            #pragma unroll
            for (int bt = 0; bt < 8; bt++) {
                uint32_t off = bRow[bt] + ((kOff + bCol) ^ bXor[bt]);
                ldsm_x4(bf[bt][0], bf[bt][1], bf[bt][2], bf[bt][3], dW + off);
            }
            uint32_t ah[2][4];
            #pragma unroll
            for (int mt = 0; mt < 2; mt++) {
                uint32_t off = aRow[mt] + ((kOff + aCol) ^ aXor[mt]);
                ldsm_x4(ah[mt][0], ah[mt][1], ah[mt][2], ah[mt][3], dA + off);
            }
            #pragma unroll
            for (int bt = 0; bt < 8; bt++) {
                #pragma unroll
                for (int mt = 0; mt < 2; mt++) {
                    mma_f16(acc[mt][2 * bt + 0], ah[mt][0], ah[mt][1], ah[mt][2], ah[mt][3],
                            bf[bt][0], bf[bt][1]);
                    mma_f16(acc[mt][2 * bt + 1], ah[mt][0], ah[mt][1], ah[mt][2], ah[mt][3],
                            bf[bt][2], bf[bt][3]);
                }
            }
        }
        if (lid == 0) mbar_arrive(EMPTYB + 8 * s);
        if (++s == NSTAGE) { s = 0; ph ^= 1; }
    }

    // ------------------------- epilogue -------------------------
    const float scl = *scale_p;
    const float zp  = *zp_p;
    const int mRow0 = mb * MT + wm * 32;
    const int nCol0 = nbp * NT + wn * 128;

    #pragma unroll
    for (int mt = 0; mt < 2; mt++) {
        const int r0 = mRow0 + mt * 16 + (lid >> 2);
        const int r1 = r0 + 8;
        const float base0 = scl * (8.0f - zp) * g_rowsum[r0];
        const float base1 = scl * (8.0f - zp) * g_rowsum[r1];
        float* o0 = out + (size_t)r0 * NDIM;
        float* o1 = out + (size_t)r1 * NDIM;
        #pragma unroll
        for (int nt = 0; nt < 16; nt++) {
            const int c = nCol0 + nt * 8 + 2 * (lid & 3);
            const float2 bv = *reinterpret_cast<const float2*>(bias + c);
            float2 v0, v1;
            v0.x = fmaf(scl, acc[mt][nt][0], base0 + bv.x);
            v0.y = fmaf(scl, acc[mt][nt][1], base0 + bv.y);
            v1.x = fmaf(scl, acc[mt][nt][2], base1 + bv.x);
            v1.y = fmaf(scl, acc[mt][nt][3], base1 + bv.y);
            *reinterpret_cast<float2*>(o0 + c) = v0;
            *reinterpret_cast<float2*>(o1 + c) = v1;
        }
    }
}

// ---------------------------------------------------------------------------
// kernel_launch
// ---------------------------------------------------------------------------
extern "C" void kernel_launch(void* const* d_in, const int* in_sizes, int n_in,
                              void* d_out, int out_size)
{
    (void)in_sizes; (void)n_in; (void)out_size;
    const float* x     = (const float*)d_in[0];
    const int*   wq    = (const int*)  d_in[1];
    const float* scale = (const float*)d_in[2];
    const float* zp    = (const float*)d_in[3];
    const float* bias  = (const float*)d_in[4];
    float* out = (float*)d_out;

    // Fused prep: 8192 x-row blocks + 8192 weight blocks (8 elems/thread)
    prep_kernel<<<MDIM + WCONV_BLOCKS, 256>>>(x, wq);

    cudaFuncSetAttribute(qgemm_kernel,
                         cudaFuncAttributeMaxDynamicSharedMemorySize, SMEM_TOTAL);
    dim3 grid(NDIM / NT, MDIM / MT);   // (16, 64)
    qgemm_kernel<<<grid, 288, SMEM_TOTAL>>>(scale, zp, bias, out);
}

// round 9
// speedup vs baseline: 1.0770x; 1.0190x over previous
#include <cuda_runtime.h>
#include <cuda_fp16.h>
#include <cstdint>
#include <cstddef>

// ---------------------------------------------------------------------------
// Problem constants (fixed shapes)
// ---------------------------------------------------------------------------
static constexpr int MDIM = 8192;   // B*S
static constexpr int NDIM = 4096;   // D_OUT
static constexpr int KDIM = 4096;   // D_IN

static constexpr int MT = 128;      // M tile per CTA
static constexpr int NT = 128;      // N tile per CTA
static constexpr int KT = 64;       // K per pipeline stage
static constexpr int KB = KDIM / KT;          // 64 K-iterations
static constexpr int NSTAGE = 3;

static constexpr int A_TILE_BYTES = MT * KT * 2;          // 16384
static constexpr int W_TILE_BYTES = NT * KT * 2;          // 16384
static constexpr int STAGE_BYTES  = A_TILE_BYTES + W_TILE_BYTES;  // 32768

static constexpr int SMEM_TOTAL = 1024 + NSTAGE * STAGE_BYTES;    // 99328/CTA

// Weight-conversion grid: 8 elements per thread, 256 threads per block.
static constexpr int WCONV_BLOCKS = NDIM * KDIM / 8 / 256;        // 8192

// ---------------------------------------------------------------------------
// Scratch (device globals). Pre-swizzled (SW128) SMEM-ready tile blocks:
//   A (x in fp16):   [mb(64)][kb(64)] blocks of 128 rows x 128B, 16KB each
//   W (q-8 in fp16): [nb(32)][kb(64)] blocks of 128 rows x 128B, 16KB each
// ---------------------------------------------------------------------------
__device__ __align__(1024) unsigned char g_Ah[(size_t)MDIM * KDIM * 2];
__device__ __align__(1024) unsigned char g_Wb[(size_t)NDIM * KDIM * 2];
__device__ float g_rowsum[MDIM];

// ---------------------------------------------------------------------------
// PTX helpers (base PTX only — nothing 'a'-gated)
// ---------------------------------------------------------------------------
__device__ __forceinline__ uint32_t smem_u32(const void* p) {
    uint32_t a;
    asm("{ .reg .u64 t; cvta.to.shared.u64 t, %1; cvt.u32.u64 %0, t; }"
        : "=r"(a) : "l"(p));
    return a;
}

__device__ __forceinline__ uint32_t swz(uint32_t b) {
    return b ^ ((b >> 3) & 0x70);
}

__device__ __forceinline__ void mbar_init(uint32_t mbar, uint32_t cnt) {
    asm volatile("mbarrier.init.shared.b64 [%0], %1;" :: "r"(mbar), "r"(cnt) : "memory");
}

__device__ __forceinline__ void mbar_arrive(uint32_t mbar) {
    asm volatile("mbarrier.arrive.shared.b64 _, [%0];" :: "r"(mbar) : "memory");
}

__device__ __forceinline__ void mbar_expect_tx(uint32_t mbar, uint32_t bytes) {
    asm volatile("mbarrier.arrive.expect_tx.shared.b64 _, [%0], %1;"
                 :: "r"(mbar), "r"(bytes) : "memory");
}

__device__ __forceinline__ void bar_wait(uint32_t mbar, uint32_t parity) {
    uint32_t done;
    asm volatile("{\n .reg .pred p;\n"
                 " mbarrier.try_wait.parity.acquire.cta.shared::cta.b64 p, [%1], %2;\n"
                 " selp.b32 %0, 1, 0, p;\n}"
                 : "=r"(done) : "r"(mbar), "r"(parity) : "memory");
    while (!done) {
        asm volatile("{\n .reg .pred p;\n"
                     " mbarrier.try_wait.parity.acquire.cta.shared::cta.b64 p, [%1], %2, 0x989680;\n"
                     " selp.b32 %0, 1, 0, p;\n}"
                     : "=r"(done) : "r"(mbar), "r"(parity) : "memory");
    }
}

__device__ __forceinline__ void bulk_g2s(uint32_t dst_smem, const void* src,
                                         uint32_t bytes, uint32_t mbar) {
    asm volatile(
        "cp.async.bulk.shared::cluster.global.mbarrier::complete_tx::bytes "
        "[%0], [%1], %2, [%3];"
        :: "r"(dst_smem), "l"(src), "r"(bytes), "r"(mbar) : "memory");
}

__device__ __forceinline__ void ldsm_x4(uint32_t& r0, uint32_t& r1,
                                        uint32_t& r2, uint32_t& r3, uint32_t addr) {
    asm volatile("ldmatrix.sync.aligned.m8n8.x4.shared.b16 {%0,%1,%2,%3}, [%4];"
                 : "=r"(r0), "=r"(r1), "=r"(r2), "=r"(r3) : "r"(addr));
}

__device__ __forceinline__ void mma_f16(float* c, uint32_t a0, uint32_t a1,
                                        uint32_t a2, uint32_t a3,
                                        uint32_t b0, uint32_t b1) {
    asm volatile("mma.sync.aligned.m16n8k16.row.col.f32.f16.f16.f32 "
                 "{%0,%1,%2,%3}, {%4,%5,%6,%7}, {%8,%9}, {%0,%1,%2,%3};"
                 : "+f"(c[0]), "+f"(c[1]), "+f"(c[2]), "+f"(c[3])
                 : "r"(a0), "r"(a1), "r"(a2), "r"(a3), "r"(b0), "r"(b1));
}

__device__ __forceinline__ uint32_t pack_h2f(float lo, float hi) {
    __half2 t = __floats2half2_rn(lo, hi);
    return *reinterpret_cast<uint32_t*>(&t);
}

// ---------------------------------------------------------------------------
// Fused prep: blocks [0, MDIM) convert x rows; blocks [MDIM, MDIM+WCONV_BLOCKS)
// convert weights (8 elems/thread).
// ---------------------------------------------------------------------------
__global__ void prep_kernel(const float* __restrict__ x, const int* __restrict__ q) {
    if (blockIdx.x < MDIM) {
        // ---- x fp32 -> fp16 plane (swizzled) + exact fp32 row sum ----
        const int m = blockIdx.x;
        const int t = threadIdx.x;    // 256 threads
        const float4* row = reinterpret_cast<const float4*>(x + (size_t)m * KDIM);
        const int mbb = m >> 7;
        const int r   = m & 127;
        const size_t abase = (size_t)mbb * ((size_t)KB * A_TILE_BYTES);

        float sum = 0.f;
        #pragma unroll
        for (int i = 0; i < 4; i++) {
            int g = t + i * 256;
            float4 v = row[g];
            sum += (v.x + v.y) + (v.z + v.w);

            int k0 = g << 2;
            int kb = k0 >> 6;
            int c0 = k0 & 63;
            size_t off = abase + (size_t)kb * A_TILE_BYTES
                       + swz((uint32_t)(r * 128 + c0 * 2));
            *reinterpret_cast<uint2*>(g_Ah + off) =
                make_uint2(pack_h2f(v.x, v.y), pack_h2f(v.z, v.w));
        }

        #pragma unroll
        for (int o = 16; o; o >>= 1) sum += __shfl_xor_sync(0xFFFFFFFFu, sum, o);
        __shared__ float ws[8];
        if ((t & 31) == 0) ws[t >> 5] = sum;
        __syncthreads();
        if (t == 0) {
            float s = 0.f;
            #pragma unroll
            for (int i = 0; i < 8; i++) s += ws[i];
            g_rowsum[m] = s;
        }
    } else {
        // ---- weight int32 (0..15) -> fp16 (q-8, exact), SW128 blocks ----
        int idx = (blockIdx.x - MDIM) * blockDim.x + threadIdx.x; // 8 elems/thr
        int n  = idx >> 9;            // 512 groups of 8 per row
        int k0 = (idx & 511) << 3;

        const int4* p = reinterpret_cast<const int4*>(q + (size_t)n * KDIM + k0);
        int4 a = p[0], b = p[1];
        uint32_t w0 = pack_h2f((float)(a.x - 8), (float)(a.y - 8));
        uint32_t w1 = pack_h2f((float)(a.z - 8), (float)(a.w - 8));
        uint32_t w2 = pack_h2f((float)(b.x - 8), (float)(b.y - 8));
        uint32_t w3 = pack_h2f((float)(b.z - 8), (float)(b.w - 8));

        int nb = n >> 7;              // 128-row N block
        int r  = n & 127;
        int kb = k0 >> 6;
        int c0 = k0 & 63;
        size_t off = ((size_t)(nb * KB + kb)) * W_TILE_BYTES
                   + swz((uint32_t)(r * 128 + c0 * 2));
        *reinterpret_cast<uint4*>(g_Wb + off) = make_uint4(w0, w1, w2, w3);
    }
}

// ---------------------------------------------------------------------------
// GEMM: 128x128 CTA tile, 2 CTAs/SM. 4 compute warps (each 32x128 of the
// tile) + 1 producer warp = 160 threads. KT=64 / NSTAGE=3.
// Per-SMSP mix is identical to the 128x256 kernel, but the 2 compute warps
// per SMSP now come from INDEPENDENT CTAs -> decorrelated barrier stalls.
// ---------------------------------------------------------------------------
__global__ void __launch_bounds__(160, 2)
qgemm_kernel(const float* __restrict__ scale_p,
             const float* __restrict__ zp_p,
             const float* __restrict__ bias,
             float* __restrict__ out)
{
    extern __shared__ __align__(1024) unsigned char smem[];
    const uint32_t sb = smem_u32(smem);
    const int tid = threadIdx.x;
    const int wid = tid >> 5;            // 0..4
    const int lid = tid & 31;
    const int mb  = blockIdx.y;          // 0..63
    const int nb  = blockIdx.x;          // 0..31

    const uint32_t FULLB  = sb;          // 3 x 8B
    const uint32_t EMPTYB = sb + 32;     // 3 x 8B
    const uint32_t TILE0  = sb + 1024;

    if (tid == 0) {
        #pragma unroll
        for (int s = 0; s < NSTAGE; s++) {
            mbar_init(FULLB  + 8 * s, 1);
            mbar_init(EMPTYB + 8 * s, 4);   // one arrive per compute warp
        }
        asm volatile("fence.proxy.async.shared::cta;" ::: "memory");
    }
    __syncthreads();

    if (wid < 4 && lid == 0) {
        #pragma unroll
        for (int s = 0; s < NSTAGE; s++) mbar_arrive(EMPTYB + 8 * s);
    }

    if (wid == 4) {
        // ------------------------- producer -------------------------
        if (lid == 0) {
            const unsigned char* aB = g_Ah + (size_t)mb * ((size_t)KB * A_TILE_BYTES);
            const unsigned char* wB = g_Wb + (size_t)nb * ((size_t)KB * W_TILE_BYTES);
            int s = 0, ph = 0;
            for (int kb = 0; kb < KB; kb++) {
                bar_wait(EMPTYB + 8 * s, ph);
                mbar_expect_tx(FULLB + 8 * s, STAGE_BYTES);
                uint32_t d = TILE0 + s * STAGE_BYTES;
                bulk_g2s(d,                aB + (size_t)kb * A_TILE_BYTES,
                         A_TILE_BYTES, FULLB + 8 * s);
                bulk_g2s(d + A_TILE_BYTES, wB + (size_t)kb * W_TILE_BYTES,
                         W_TILE_BYTES, FULLB + 8 * s);
                if (++s == NSTAGE) { s = 0; ph ^= 1; }
            }
        }
        return;
    }

    // ------------------------- compute warps -------------------------
    const int wm = wid;              // M sub-tile (32 rows), warp covers all 128 N
    const int g  = lid >> 3;         // ldmatrix lane group 0..3
    const int lr = lid & 7;

    uint32_t aRow[2], aXor[2];
    #pragma unroll
    for (int mt = 0; mt < 2; mt++) {
        int r = wm * 32 + mt * 16 + (g & 1) * 8 + lr;
        aRow[mt] = (uint32_t)(r * 128);
        aXor[mt] = (uint32_t)((r & 7) << 4);
    }
    uint32_t bRow[8], bXor[8];
    #pragma unroll
    for (int bt = 0; bt < 8; bt++) {
        int r = bt * 16 + (g >> 1) * 8 + lr;     // N rows 0..127
        bRow[bt] = (uint32_t)(r * 128);
        bXor[bt] = (uint32_t)((r & 7) << 4);
    }
    const uint32_t aCol = (uint32_t)((g >> 1) * 16);
    const uint32_t bCol = (uint32_t)((g & 1) * 16);

    float acc[2][16][4];
    #pragma unroll
    for (int mt = 0; mt < 2; mt++)
        #pragma unroll
        for (int nt = 0; nt < 16; nt++)
            #pragma unroll
            for (int j = 0; j < 4; j++) acc[mt][nt][j] = 0.f;

    int s = 0, ph = 0;
    for (int kb = 0; kb < KB; kb++) {
        bar_wait(FULLB + 8 * s, ph);
        const uint32_t dA = TILE0 + s * STAGE_BYTES;
        const uint32_t dW = dA + A_TILE_BYTES;

        #pragma unroll
        for (int ks = 0; ks < 4; ks++) {
            const uint32_t kOff = (uint32_t)(ks * 32);

            uint32_t bf[8][4];
            #pragma unroll
            for (int bt = 0; bt < 8; bt++) {
                uint32_t off = bRow[bt] + ((kOff + bCol) ^ bXor[bt]);
                ldsm_x4(bf[bt][0], bf[bt][1], bf[bt][2], bf[bt][3], dW + off);
            }
            uint32_t ah[2][4];
            #pragma unroll
            for (int mt = 0; mt < 2; mt++) {
                uint32_t off = aRow[mt] + ((kOff + aCol) ^ aXor[mt]);
                ldsm_x4(ah[mt][0], ah[mt][1], ah[mt][2], ah[mt][3], dA + off);
            }
            #pragma unroll
            for (int bt = 0; bt < 8; bt++) {
                #pragma unroll
                for (int mt = 0; mt < 2; mt++) {
                    mma_f16(acc[mt][2 * bt + 0], ah[mt][0], ah[mt][1], ah[mt][2], ah[mt][3],
                            bf[bt][0], bf[bt][1]);
                    mma_f16(acc[mt][2 * bt + 1], ah[mt][0], ah[mt][1], ah[mt][2], ah[mt][3],
                            bf[bt][2], bf[bt][3]);
                }
            }
        }
        if (lid == 0) mbar_arrive(EMPTYB + 8 * s);
        if (++s == NSTAGE) { s = 0; ph ^= 1; }
    }

    // ------------------------- epilogue -------------------------
    const float scl = *scale_p;
    const float zp  = *zp_p;
    const int mRow0 = mb * MT + wm * 32;
    const int nCol0 = nb * NT;

    #pragma unroll
    for (int mt = 0; mt < 2; mt++) {
        const int r0 = mRow0 + mt * 16 + (lid >> 2);
        const int r1 = r0 + 8;
        const float base0 = scl * (8.0f - zp) * g_rowsum[r0];
        const float base1 = scl * (8.0f - zp) * g_rowsum[r1];
        float* o0 = out + (size_t)r0 * NDIM;
        float* o1 = out + (size_t)r1 * NDIM;
        #pragma unroll
        for (int nt = 0; nt < 16; nt++) {
            const int c = nCol0 + nt * 8 + 2 * (lid & 3);
            const float2 bv = *reinterpret_cast<const float2*>(bias + c);
            float2 v0, v1;
            v0.x = fmaf(scl, acc[mt][nt][0], base0 + bv.x);
            v0.y = fmaf(scl, acc[mt][nt][1], base0 + bv.y);
            v1.x = fmaf(scl, acc[mt][nt][2], base1 + bv.x);
            v1.y = fmaf(scl, acc[mt][nt][3], base1 + bv.y);
            *reinterpret_cast<float2*>(o0 + c) = v0;
            *reinterpret_cast<float2*>(o1 + c) = v1;
        }
    }
}

// ---------------------------------------------------------------------------
// kernel_launch
// ---------------------------------------------------------------------------
extern "C" void kernel_launch(void* const* d_in, const int* in_sizes, int n_in,
                              void* d_out, int out_size)
{
    (void)in_sizes; (void)n_in; (void)out_size;
    const float* x     = (const float*)d_in[0];
    const int*   wq    = (const int*)  d_in[1];
    const float* scale = (const float*)d_in[2];
    const float* zp    = (const float*)d_in[3];
    const float* bias  = (const float*)d_in[4];
    float* out = (float*)d_out;

    // Fused prep: 8192 x-row blocks + 8192 weight blocks (8 elems/thread)
    prep_kernel<<<MDIM + WCONV_BLOCKS, 256>>>(x, wq);

    cudaFuncSetAttribute(qgemm_kernel,
                         cudaFuncAttributeMaxDynamicSharedMemorySize, SMEM_TOTAL);
    dim3 grid(NDIM / NT, MDIM / MT);   // (32, 64)
    qgemm_kernel<<<grid, 160, SMEM_TOTAL>>>(scale, zp, bias, out);
}

// round 10
// speedup vs baseline: 1.0774x; 1.0004x over previous
#include <cuda_runtime.h>
#include <cuda_fp16.h>
#include <cstdint>
#include <cstddef>

// ---------------------------------------------------------------------------
// Problem constants (fixed shapes)
// ---------------------------------------------------------------------------
static constexpr int MDIM = 8192;   // B*S
static constexpr int NDIM = 4096;   // D_OUT
static constexpr int KDIM = 4096;   // D_IN

static constexpr int MT = 128;      // M tile per CTA
static constexpr int NT = 128;      // N tile per CTA
static constexpr int KT = 64;       // K per pipeline stage
static constexpr int KB = KDIM / KT;          // 64 K-iterations
static constexpr int NSTAGE = 3;

static constexpr int A_TILE_BYTES = MT * KT * 2;          // 16384
static constexpr int W_TILE_BYTES = NT * KT * 2;          // 16384
static constexpr int STAGE_BYTES  = A_TILE_BYTES + W_TILE_BYTES;  // 32768

static constexpr int SMEM_TOTAL = 1024 + NSTAGE * STAGE_BYTES;    // 99328/CTA

// Weight-conversion grid: 8 elements per thread, 256 threads per block.
static constexpr int WCONV_BLOCKS = NDIM * KDIM / 8 / 256;        // 8192

// ---------------------------------------------------------------------------
// Scratch (device globals). Pre-swizzled (SW128) SMEM-ready tile blocks:
//   A (x in fp16):   [mb(64)][kb(64)] blocks of 128 rows x 128B, 16KB each
//   W (q-8 in fp16): [nb(32)][kb(64)] blocks of 128 rows x 128B, 16KB each
// ---------------------------------------------------------------------------
__device__ __align__(1024) unsigned char g_Ah[(size_t)MDIM * KDIM * 2];
__device__ __align__(1024) unsigned char g_Wb[(size_t)NDIM * KDIM * 2];
__device__ float g_rowsum[MDIM];

// ---------------------------------------------------------------------------
// PTX helpers (base PTX only — nothing 'a'-gated)
// ---------------------------------------------------------------------------
__device__ __forceinline__ uint32_t smem_u32(const void* p) {
    uint32_t a;
    asm("{ .reg .u64 t; cvta.to.shared.u64 t, %1; cvt.u32.u64 %0, t; }"
        : "=r"(a) : "l"(p));
    return a;
}

__device__ __forceinline__ uint32_t swz(uint32_t b) {
    return b ^ ((b >> 3) & 0x70);
}

__device__ __forceinline__ void mbar_init(uint32_t mbar, uint32_t cnt) {
    asm volatile("mbarrier.init.shared.b64 [%0], %1;" :: "r"(mbar), "r"(cnt) : "memory");
}

__device__ __forceinline__ void mbar_arrive(uint32_t mbar) {
    asm volatile("mbarrier.arrive.shared.b64 _, [%0];" :: "r"(mbar) : "memory");
}

__device__ __forceinline__ void mbar_expect_tx(uint32_t mbar, uint32_t bytes) {
    asm volatile("mbarrier.arrive.expect_tx.shared.b64 _, [%0], %1;"
                 :: "r"(mbar), "r"(bytes) : "memory");
}

__device__ __forceinline__ void bar_wait(uint32_t mbar, uint32_t parity) {
    uint32_t done;
    asm volatile("{\n .reg .pred p;\n"
                 " mbarrier.try_wait.parity.acquire.cta.shared::cta.b64 p, [%1], %2;\n"
                 " selp.b32 %0, 1, 0, p;\n}"
                 : "=r"(done) : "r"(mbar), "r"(parity) : "memory");
    while (!done) {
        asm volatile("{\n .reg .pred p;\n"
                     " mbarrier.try_wait.parity.acquire.cta.shared::cta.b64 p, [%1], %2, 0x989680;\n"
                     " selp.b32 %0, 1, 0, p;\n}"
                     : "=r"(done) : "r"(mbar), "r"(parity) : "memory");
    }
}

__device__ __forceinline__ void bulk_g2s(uint32_t dst_smem, const void* src,
                                         uint32_t bytes, uint32_t mbar) {
    asm volatile(
        "cp.async.bulk.shared::cluster.global.mbarrier::complete_tx::bytes "
        "[%0], [%1], %2, [%3];"
        :: "r"(dst_smem), "l"(src), "r"(bytes), "r"(mbar) : "memory");
}

__device__ __forceinline__ void ldsm_x4(uint32_t& r0, uint32_t& r1,
                                        uint32_t& r2, uint32_t& r3, uint32_t addr) {
    asm volatile("ldmatrix.sync.aligned.m8n8.x4.shared.b16 {%0,%1,%2,%3}, [%4];"
                 : "=r"(r0), "=r"(r1), "=r"(r2), "=r"(r3) : "r"(addr));
}

__device__ __forceinline__ void mma_f16(float* c, uint32_t a0, uint32_t a1,
                                        uint32_t a2, uint32_t a3,
                                        uint32_t b0, uint32_t b1) {
    asm volatile("mma.sync.aligned.m16n8k16.row.col.f32.f16.f16.f32 "
                 "{%0,%1,%2,%3}, {%4,%5,%6,%7}, {%8,%9}, {%0,%1,%2,%3};"
                 : "+f"(c[0]), "+f"(c[1]), "+f"(c[2]), "+f"(c[3])
                 : "r"(a0), "r"(a1), "r"(a2), "r"(a3), "r"(b0), "r"(b1));
}

__device__ __forceinline__ uint32_t pack_h2f(float lo, float hi) {
    __half2 t = __floats2half2_rn(lo, hi);
    return *reinterpret_cast<uint32_t*>(&t);
}

// ---------------------------------------------------------------------------
// Fused prep: blocks [0, MDIM) convert x rows; blocks [MDIM, MDIM+WCONV_BLOCKS)
// convert weights (8 elems/thread).
// ---------------------------------------------------------------------------
__global__ void prep_kernel(const float* __restrict__ x, const int* __restrict__ q) {
    if (blockIdx.x < MDIM) {
        // ---- x fp32 -> fp16 plane (swizzled) + exact fp32 row sum ----
        const int m = blockIdx.x;
        const int t = threadIdx.x;    // 256 threads
        const float4* row = reinterpret_cast<const float4*>(x + (size_t)m * KDIM);
        const int mbb = m >> 7;
        const int r   = m & 127;
        const size_t abase = (size_t)mbb * ((size_t)KB * A_TILE_BYTES);

        float sum = 0.f;
        #pragma unroll
        for (int i = 0; i < 4; i++) {
            int g = t + i * 256;
            float4 v = row[g];
            sum += (v.x + v.y) + (v.z + v.w);

            int k0 = g << 2;
            int kb = k0 >> 6;
            int c0 = k0 & 63;
            size_t off = abase + (size_t)kb * A_TILE_BYTES
                       + swz((uint32_t)(r * 128 + c0 * 2));
            *reinterpret_cast<uint2*>(g_Ah + off) =
                make_uint2(pack_h2f(v.x, v.y), pack_h2f(v.z, v.w));
        }

        #pragma unroll
        for (int o = 16; o; o >>= 1) sum += __shfl_xor_sync(0xFFFFFFFFu, sum, o);
        __shared__ float ws[8];
        if ((t & 31) == 0) ws[t >> 5] = sum;
        __syncthreads();
        if (t == 0) {
            float s = 0.f;
            #pragma unroll
            for (int i = 0; i < 8; i++) s += ws[i];
            g_rowsum[m] = s;
        }
    } else {
        // ---- weight int32 (0..15) -> fp16 (q-8, exact), SW128 blocks ----
        int idx = (blockIdx.x - MDIM) * blockDim.x + threadIdx.x; // 8 elems/thr
        int n  = idx >> 9;            // 512 groups of 8 per row
        int k0 = (idx & 511) << 3;

        const int4* p = reinterpret_cast<const int4*>(q + (size_t)n * KDIM + k0);
        int4 a = p[0], b = p[1];
        uint32_t w0 = pack_h2f((float)(a.x - 8), (float)(a.y - 8));
        uint32_t w1 = pack_h2f((float)(a.z - 8), (float)(a.w - 8));
        uint32_t w2 = pack_h2f((float)(b.x - 8), (float)(b.y - 8));
        uint32_t w3 = pack_h2f((float)(b.z - 8), (float)(b.w - 8));

        int nb = n >> 7;              // 128-row N block
        int r  = n & 127;
        int kb = k0 >> 6;
        int c0 = k0 & 63;
        size_t off = ((size_t)(nb * KB + kb)) * W_TILE_BYTES
                   + swz((uint32_t)(r * 128 + c0 * 2));
        *reinterpret_cast<uint4*>(g_Wb + off) = make_uint4(w0, w1, w2, w3);
    }
}

// ---------------------------------------------------------------------------
// GEMM: 128x128 CTA tile, 2 CTAs/SM, 4 compute warps + 1 producer.
// K-offset staggering: each CTA walks kb in rotated order (it+koff)%64 so
// co-resident CTAs' stage-boundary waits interleave instead of colliding.
// ---------------------------------------------------------------------------
__global__ void __launch_bounds__(160, 2)
qgemm_kernel(const float* __restrict__ scale_p,
             const float* __restrict__ zp_p,
             const float* __restrict__ bias,
             float* __restrict__ out)
{
    extern __shared__ __align__(1024) unsigned char smem[];
    const uint32_t sb = smem_u32(smem);
    const int tid = threadIdx.x;
    const int wid = tid >> 5;            // 0..4
    const int lid = tid & 31;
    const int mb  = blockIdx.y;          // 0..63
    const int nb  = blockIdx.x;          // 0..31

    // Phase stagger: co-resident CTAs (bid, bid+148) get different koff
    // since (bid>>2) differs by 37 (37 mod 4 != 0).
    const int bid  = mb * (int)gridDim.x + nb;
    const int koff = ((bid >> 2) & 3) << 4;   // 0, 16, 32, 48

    const uint32_t FULLB  = sb;          // 3 x 8B
    const uint32_t EMPTYB = sb + 32;     // 3 x 8B
    const uint32_t TILE0  = sb + 1024;

    if (tid == 0) {
        #pragma unroll
        for (int s = 0; s < NSTAGE; s++) {
            mbar_init(FULLB  + 8 * s, 1);
            mbar_init(EMPTYB + 8 * s, 4);   // one arrive per compute warp
        }
        asm volatile("fence.proxy.async.shared::cta;" ::: "memory");
    }
    __syncthreads();

    if (wid < 4 && lid == 0) {
        #pragma unroll
        for (int s = 0; s < NSTAGE; s++) mbar_arrive(EMPTYB + 8 * s);
    }

    if (wid == 4) {
        // ------------------------- producer -------------------------
        if (lid == 0) {
            const unsigned char* aB = g_Ah + (size_t)mb * ((size_t)KB * A_TILE_BYTES);
            const unsigned char* wB = g_Wb + (size_t)nb * ((size_t)KB * W_TILE_BYTES);
            int s = 0, ph = 0;
            for (int it = 0; it < KB; it++) {
                int kb = (it + koff) & (KB - 1);
                bar_wait(EMPTYB + 8 * s, ph);
                mbar_expect_tx(FULLB + 8 * s, STAGE_BYTES);
                uint32_t d = TILE0 + s * STAGE_BYTES;
                bulk_g2s(d,                aB + (size_t)kb * A_TILE_BYTES,
                         A_TILE_BYTES, FULLB + 8 * s);
                bulk_g2s(d + A_TILE_BYTES, wB + (size_t)kb * W_TILE_BYTES,
                         W_TILE_BYTES, FULLB + 8 * s);
                if (++s == NSTAGE) { s = 0; ph ^= 1; }
            }
        }
        return;
    }

    // ------------------------- compute warps -------------------------
    const int wm = wid;              // M sub-tile (32 rows), warp covers all 128 N
    const int g  = lid >> 3;         // ldmatrix lane group 0..3
    const int lr = lid & 7;

    uint32_t aRow[2], aXor[2];
    #pragma unroll
    for (int mt = 0; mt < 2; mt++) {
        int r = wm * 32 + mt * 16 + (g & 1) * 8 + lr;
        aRow[mt] = (uint32_t)(r * 128);
        aXor[mt] = (uint32_t)((r & 7) << 4);
    }
    uint32_t bRow[8], bXor[8];
    #pragma unroll
    for (int bt = 0; bt < 8; bt++) {
        int r = bt * 16 + (g >> 1) * 8 + lr;     // N rows 0..127
        bRow[bt] = (uint32_t)(r * 128);
        bXor[bt] = (uint32_t)((r & 7) << 4);
    }
    const uint32_t aCol = (uint32_t)((g >> 1) * 16);
    const uint32_t bCol = (uint32_t)((g & 1) * 16);

    float acc[2][16][4];
    #pragma unroll
    for (int mt = 0; mt < 2; mt++)
        #pragma unroll
        for (int nt = 0; nt < 16; nt++)
            #pragma unroll
            for (int j = 0; j < 4; j++) acc[mt][nt][j] = 0.f;

    int s = 0, ph = 0;
    for (int it = 0; it < KB; it++) {
        bar_wait(FULLB + 8 * s, ph);
        const uint32_t dA = TILE0 + s * STAGE_BYTES;
        const uint32_t dW = dA + A_TILE_BYTES;

        #pragma unroll
        for (int ks = 0; ks < 4; ks++) {
            const uint32_t kOff = (uint32_t)(ks * 32);

            uint32_t bf[8][4];
            #pragma unroll
            for (int bt = 0; bt < 8; bt++) {
                uint32_t off = bRow[bt] + ((kOff + bCol) ^ bXor[bt]);
                ldsm_x4(bf[bt][0], bf[bt][1], bf[bt][2], bf[bt][3], dW + off);
            }
            uint32_t ah[2][4];
            #pragma unroll
            for (int mt = 0; mt < 2; mt++) {
                uint32_t off = aRow[mt] + ((kOff + aCol) ^ aXor[mt]);
                ldsm_x4(ah[mt][0], ah[mt][1], ah[mt][2], ah[mt][3], dA + off);
            }
            #pragma unroll
            for (int bt = 0; bt < 8; bt++) {
                #pragma unroll
                for (int mt = 0; mt < 2; mt++) {
                    mma_f16(acc[mt][2 * bt + 0], ah[mt][0], ah[mt][1], ah[mt][2], ah[mt][3],
                            bf[bt][0], bf[bt][1]);
                    mma_f16(acc[mt][2 * bt + 1], ah[mt][0], ah[mt][1], ah[mt][2], ah[mt][3],
                            bf[bt][2], bf[bt][3]);
                }
            }
        }
        if (lid == 0) mbar_arrive(EMPTYB + 8 * s);
        if (++s == NSTAGE) { s = 0; ph ^= 1; }
    }

    // ------------------------- epilogue -------------------------
    const float scl = *scale_p;
    const float zp  = *zp_p;
    const int mRow0 = mb * MT + wm * 32;
    const int nCol0 = nb * NT;

    #pragma unroll
    for (int mt = 0; mt < 2; mt++) {
        const int r0 = mRow0 + mt * 16 + (lid >> 2);
        const int r1 = r0 + 8;
        const float base0 = scl * (8.0f - zp) * g_rowsum[r0];
        const float base1 = scl * (8.0f - zp) * g_rowsum[r1];
        float* o0 = out + (size_t)r0 * NDIM;
        float* o1 = out + (size_t)r1 * NDIM;
        #pragma unroll
        for (int nt = 0; nt < 16; nt++) {
            const int c = nCol0 + nt * 8 + 2 * (lid & 3);
            const float2 bv = *reinterpret_cast<const float2*>(bias + c);
            float2 v0, v1;
            v0.x = fmaf(scl, acc[mt][nt][0], base0 + bv.x);
            v0.y = fmaf(scl, acc[mt][nt][1], base0 + bv.y);
            v1.x = fmaf(scl, acc[mt][nt][2], base1 + bv.x);
            v1.y = fmaf(scl, acc[mt][nt][3], base1 + bv.y);
            *reinterpret_cast<float2*>(o0 + c) = v0;
            *reinterpret_cast<float2*>(o1 + c) = v1;
        }
    }
}

// ---------------------------------------------------------------------------
// kernel_launch
// ---------------------------------------------------------------------------
extern "C" void kernel_launch(void* const* d_in, const int* in_sizes, int n_in,
                              void* d_out, int out_size)
{
    (void)in_sizes; (void)n_in; (void)out_size;
    const float* x     = (const float*)d_in[0];
    const int*   wq    = (const int*)  d_in[1];
    const float* scale = (const float*)d_in[2];
    const float* zp    = (const float*)d_in[3];
    const float* bias  = (const float*)d_in[4];
    float* out = (float*)d_out;

    // Fused prep: 8192 x-row blocks + 8192 weight blocks (8 elems/thread)
    prep_kernel<<<MDIM + WCONV_BLOCKS, 256>>>(x, wq);

    cudaFuncSetAttribute(qgemm_kernel,
                         cudaFuncAttributeMaxDynamicSharedMemorySize, SMEM_TOTAL);
    dim3 grid(NDIM / NT, MDIM / MT);   // (32, 64)
    qgemm_kernel<<<grid, 160, SMEM_TOTAL>>>(scale, zp, bias, out);
}